// round 3
// baseline (speedup 1.0000x reference)
#include <cuda_runtime.h>

// out[b] = sum_k targets[b,k] * tb[batch_indices[1],k] * scaling[k]
// targets [8192,1024] f32, temporal_bases [16384,1024] f32,
// scaling [1024] f32, batch_indices [8192] (int32 or int64), out [8192] f32.

constexpr int K = 1024;
constexpr int B = 8192;
constexpr int T = 16384;
constexpr int THREADS = 256;          // 8 warps
constexpr int WARPS_PER_BLOCK = THREADS / 32;
constexpr int K4 = K / 4;             // 256 float4

__global__ void __launch_bounds__(THREADS)
recompose_gemv_kernel(const float* __restrict__ targets,
                      const float* __restrict__ temporal_bases,
                      const float* __restrict__ scaling,
                      const void* __restrict__ batch_indices,
                      float* __restrict__ out)
{
    __shared__ float4 w4[K4];   // 4 KiB weight vector

    // Dtype-agnostic read of batch_indices[1].
    // If stored as int64: i64 view elem 1 is the true value (in [0,T)).
    // If stored as int32: i64 view elem 1 combines random elems 2,3 ->
    // out of range w.h.p. -> fall back to i32 view elem 1.
    long long idx1 = ((const long long*)batch_indices)[1];
    if (idx1 < 0 || idx1 >= T)
        idx1 = (long long)(((const int*)batch_indices)[1]);
    if (idx1 < 0) idx1 = 0;
    if (idx1 >= T) idx1 = T - 1;      // last-resort clamp: no OOB ever

    const float4* tb4 = reinterpret_cast<const float4*>(
        temporal_bases + (size_t)idx1 * K);
    const float4* sc4 = reinterpret_cast<const float4*>(scaling);

    const int tid = threadIdx.x;
    {
        float4 t = tb4[tid];
        float4 s = sc4[tid];
        w4[tid] = make_float4(t.x * s.x, t.y * s.y, t.z * s.z, t.w * s.w);
    }
    __syncthreads();

    // One warp per row of targets.
    const int warp = tid >> 5;
    const int lane = tid & 31;
    const int row  = blockIdx.x * WARPS_PER_BLOCK + warp;
    if (row >= B) return;

    const float4* tg4 = reinterpret_cast<const float4*>(
        targets + (size_t)row * K);

    // 8 independent 16B loads per lane -> MLP=8, fully coalesced.
    float acc = 0.0f;
#pragma unroll
    for (int i = 0; i < K4 / 32; ++i) {
        float4 a = tg4[lane + i * 32];
        float4 b = w4[lane + i * 32];
        acc += a.x * b.x + a.y * b.y + a.z * b.z + a.w * b.w;
    }

    // Butterfly reduce within the warp.
#pragma unroll
    for (int off = 16; off > 0; off >>= 1)
        acc += __shfl_xor_sync(0xffffffffu, acc, off);

    if (lane == 0)
        out[row] = acc;
}

extern "C" void kernel_launch(void* const* d_in, const int* in_sizes, int n_in,
                              void* d_out, int out_size)
{
    // Identify inputs by element count — robust to metadata ordering.
    const float* targets = nullptr;
    const float* temporal_bases = nullptr;
    const float* scaling = nullptr;
    const void*  batch_indices = nullptr;

    for (int i = 0; i < n_in; ++i) {
        switch (in_sizes[i]) {
            case B * K:     targets        = (const float*)d_in[i]; break;  // 8388608
            case T * K:     temporal_bases = (const float*)d_in[i]; break;  // 16777216
            case K:         scaling        = (const float*)d_in[i]; break;  // 1024
            case B:         batch_indices  = d_in[i];               break;  // 8192
            default: break;
        }
    }

    float* out = (float*)d_out;

    dim3 grid(B / WARPS_PER_BLOCK);   // 1024 blocks
    recompose_gemv_kernel<<<grid, THREADS>>>(targets, temporal_bases,
                                             scaling, batch_indices, out);
}